// round 14
// baseline (speedup 1.0000x reference)
#include <cuda_runtime.h>
#include <cuda_bf16.h>
#include <math.h>

// ----------------------------------------------------------------------------
// SpectralLoss on GB300 — register radix-8 FFT + owner-computes radial binning.
// K0: fill twiddle tables (accurate sincosf), 1 tiny block.
// K1: T-mean + packed row-pair FFT + Hermitian split -> g_fft[k=0..256].
// K2: column FFT (4 cols/block); power written back to shared; thread r
//     GATHERS its bin's ky-runs (exact integer ranges) — no atomics at all.
// K3: 65 blocks level-1 reduce; last arriving block computes the loss scalar.
// ----------------------------------------------------------------------------

#define N512 512
#define NB   16
#define NT   8
#define RS   264                  // g_fft row stride (float2)
#define K2_BLOCKS (NB * 65)       // 1040
#define FPAD(i) ((i) + (((i) >> 6) << 3))   // +8 pad per 64 slots

__device__ float2 g_fft[(size_t)NB * N512 * RS];     // ~17.3 MB
__device__ float  g_part [K2_BLOCKS * 256];          // [block][bin]
__device__ float  g_part2[65 * 256];                 // level-1 sums [blk][bin]
__device__ float  g_cnt  [65 * 256];                 // [group][bin]
__device__ unsigned g_arrive;
__device__ float2 g_tw1[7 * 64];                     // W512^{t*q}, q=1..7
__device__ float2 g_tw2[8 * 7];                      // W64^{u*r},  r=1..7

__device__ __forceinline__ float2 cadd(float2 a, float2 b){ return make_float2(a.x+b.x, a.y+b.y); }
__device__ __forceinline__ float2 csub(float2 a, float2 b){ return make_float2(a.x-b.x, a.y-b.y); }
__device__ __forceinline__ float2 cmul(float2 a, float2 b){
    return make_float2(a.x*b.x - a.y*b.y, a.x*b.y + a.y*b.x);
}
__device__ __forceinline__ float2 mul_mi(float2 a){ return make_float2(a.y, -a.x); }
__device__ __forceinline__ float2 mul_w81(float2 a){
    const float C = 0.70710678118654752f;
    return make_float2(C*(a.x+a.y), C*(a.y-a.x));
}
__device__ __forceinline__ float2 mul_w83(float2 a){
    const float C = 0.70710678118654752f;
    return make_float2(C*(a.y-a.x), -C*(a.x+a.y));
}

__device__ __forceinline__ void dft8(const float2* a, float2* X){
    float2 t0 = cadd(a[0], a[4]), t1 = cadd(a[1], a[5]);
    float2 t2 = cadd(a[2], a[6]), t3 = cadd(a[3], a[7]);
    float2 u0 = csub(a[0], a[4]);
    float2 u1 = mul_w81(csub(a[1], a[5]));
    float2 u2 = mul_mi (csub(a[2], a[6]));
    float2 u3 = mul_w83(csub(a[3], a[7]));
    float2 s0 = cadd(t0, t2), s1 = cadd(t1, t3);
    float2 d0 = csub(t0, t2), d1 = mul_mi(csub(t1, t3));
    float2 e0 = cadd(u0, u2), e1 = cadd(u1, u3);
    float2 f0 = csub(u0, u2), f1 = mul_mi(csub(u1, u3));
    X[0] = cadd(s0, s1); X[4] = csub(s0, s1);
    X[2] = cadd(d0, d1); X[6] = csub(d0, d1);
    X[1] = cadd(e0, e1); X[5] = csub(e0, e1);
    X[3] = cadd(f0, f1); X[7] = csub(f0, f1);
}

// exact integer isqrt via correctly-rounded float sqrt + fixup (n < 2^20)
__device__ __forceinline__ int isqrt_exact(int n){
    int k = (int)__fsqrt_rn((float)n);
    if (k * k > n) k--;
    else if ((k + 1) * (k + 1) <= n) k++;
    return k;
}

// ---------------- K0: twiddle tables ----------------
__global__ void k_twiddle_init(){
    const int i = threadIdx.x;
    if (i < 448){
        int q = (i >> 6) + 1, t = i & 63;
        float ang = -6.2831853071795864f * (float)(t * q) / 512.0f;
        float s, c; sincosf(ang, &s, &c);
        g_tw1[i] = make_float2(c, s);
    }
    if (i < 56){
        int u = i / 7, r = (i % 7) + 1;
        float ang = -6.2831853071795864f * (float)(u * r) / 64.0f;
        float s, c; sincosf(ang, &s, &c);
        g_tw2[i] = make_float2(c, s);
    }
}

// stage 1: a[p] = x[t + 64p] -> y_q[t] stored at 72q+t  (twiddles from g_tw1)
__device__ __forceinline__ void fft_stage1(const float2* a, int t, float* sre, float* sim){
    float2 W[8];
#pragma unroll
    for (int q = 1; q < 8; q++) W[q] = g_tw1[((q - 1) << 6) + t];
    float2 b[8];
    dft8(a, b);
    sre[t] = b[0].x; sim[t] = b[0].y;
#pragma unroll
    for (int q = 1; q < 8; q++){
        float2 c = cmul(b[q], W[q]);
        sre[72*q + t] = c.x; sim[72*q + t] = c.y;
    }
}

// stages 2+3: consumes y in shared, returns X[w] at ky = ky0 + 64w
__device__ __forceinline__ void fft_stage23(float* sre, float* sim, int t,
                                            float2* X, int* ky0_out){
    const int q = t >> 3, u = t & 7;
    float2 W[8];
#pragma unroll
    for (int r = 1; r < 8; r++) W[r] = g_tw2[u * 7 + (r - 1)];
    float2 a[8], b[8];
#pragma unroll
    for (int v = 0; v < 8; v++){
        int idx = 72*q + u + 8*v;
        a[v] = make_float2(sre[idx], sim[idx]);
    }
    dft8(a, b);
    __syncwarp();
    {   // r = 0
        int idx = 72*q + (u ^ ((2*q) & 7));
        sre[idx] = b[0].x; sim[idx] = b[0].y;
    }
#pragma unroll
    for (int r = 1; r < 8; r++){
        float2 c = cmul(b[r], W[r]);
        int swz = (2*q + (r >> 2)) & 7;
        int idx = 72*q + 8*r + (u ^ swz);
        sre[idx] = c.x; sim[idx] = c.y;
    }
    __syncwarp();
    const int r3 = u;
    const int swz = (2*q + (r3 >> 2)) & 7;
#pragma unroll
    for (int uu = 0; uu < 8; uu++){
        int idx = 72*q + 8*r3 + (uu ^ swz);
        a[uu] = make_float2(sre[idx], sim[idx]);
    }
    dft8(a, X);
    *ky0_out = q + 8*r3;
}

// ---------------- K1: T-mean + packed row-pair FFT + Hermitian split ---------
__global__ __launch_bounds__(256) void k_mean_rowfft(const float* __restrict__ in){
    __shared__ float sre[4][584], sim[4][584];
    const int tid  = threadIdx.x;
    const int team = tid >> 6;
    const int t    = tid & 63;
    const int b    = blockIdx.x >> 6;
    const int hp   = ((blockIdx.x & 63) << 2) + team;    // row pair 0..255

    const float* base = in + ((size_t)b * NT * N512 + 2 * hp) * N512;
    float2 a[8];
#pragma unroll
    for (int p = 0; p < 8; p++) a[p] = make_float2(0.f, 0.f);
#pragma unroll
    for (int tt = 0; tt < NT; tt++){
        const float* pe = base + (size_t)tt * (N512 * N512);
#pragma unroll
        for (int p = 0; p < 8; p++){
            a[p].x += pe[t + 64*p];            // even row -> re
            a[p].y += pe[N512 + t + 64*p];     // odd row  -> im
        }
    }
#pragma unroll
    for (int p = 0; p < 8; p++){ a[p].x *= 0.125f; a[p].y *= 0.125f; }

    fft_stage1(a, t, sre[team], sim[team]);
    __syncthreads();
    float2 X[8]; int ky0;
    fft_stage23(sre[team], sim[team], t, X, &ky0);
    __syncthreads();
#pragma unroll
    for (int w = 0; w < 8; w++){
        sre[team][ky0 + 72*w] = X[w].x;        // = FPAD(ky0 + 64w)
        sim[team][ky0 + 72*w] = X[w].y;
    }
    __syncthreads();

    // Hermitian split: Z = Fe + i*Fo
    float2* oute = g_fft + ((size_t)b * N512 + 2 * hp) * RS;
    float2* outo = oute + RS;
    for (int k = t; k <= 256; k += 64){
        int m = (N512 - k) & (N512 - 1);
        float2 zk = make_float2(sre[team][FPAD(k)], sim[team][FPAD(k)]);
        float2 zm = make_float2(sre[team][FPAD(m)], sim[team][FPAD(m)]);
        oute[k] = make_float2(0.5f*(zk.x + zm.x), 0.5f*(zk.y - zm.y));
        outo[k] = make_float2(0.5f*(zk.y + zm.y), 0.5f*(zm.x - zk.x));
    }
}

// ---------------- K2: column FFT (4 cols/block) + owner-computes binning -----
__global__ __launch_bounds__(256) void k_colfft_bin(){
    __shared__ float sre[4][584], sim[4][584];
    const int tid = threadIdx.x;
    const int b   = blockIdx.x / 65;
    const int g   = blockIdx.x % 65;
    const int kx0 = g << 2;

    const float2* src = g_fft + (size_t)b * (N512 * RS);
#pragma unroll
    for (int k = 0; k < 8; k++){
        int idx = tid + (k << 8);
        int row = idx >> 2, c = idx & 3;
        int kx  = kx0 + c;
        float2 v = (kx <= 256) ? src[(size_t)row * RS + kx] : make_float2(0.f, 0.f);
        sre[c][FPAD(row)] = v.x; sim[c][FPAD(row)] = v.y;
    }
    __syncthreads();

    const int team = tid >> 6, t = tid & 63;
    float2 a[8];
#pragma unroll
    for (int p = 0; p < 8; p++)
        a[p] = make_float2(sre[team][t + 72*p], sim[team][t + 72*p]);  // FPAD(t+64p)
    fft_stage1(a, t, sre[team], sim[team]);
    __syncthreads();
    float2 X[8]; int ky0;
    fft_stage23(sre[team], sim[team], t, X, &ky0);
    __syncthreads();
    // write RAW power back into sre[team], indexed by ky
#pragma unroll
    for (int w = 0; w < 8; w++)
        sre[team][ky0 + 72*w] = X[w].x * X[w].x + X[w].y * X[w].y;  // = FPAD(ky0+64w)
    __syncthreads();

    // owner-computes: thread r gathers its bin's exact ky-ranges per column.
    // bin r <=> r^2 <= dy^2+dx^2 <= (r+1)^2 - 1  (exact integer partition;
    // matches int(__fsqrt_rn) of exact-integer floats).
    const int r = tid;
    const int rsq  = r * r;
    const int rsq1 = (r + 1) * (r + 1);
    float seg = 0.f, cntv = 0.f;
#pragma unroll
    for (int c = 0; c < 4; c++){
        int kx = kx0 + c;
        if (kx > 256) break;
        int dx  = kx - 256;
        int dx2 = dx * dx;
        int m1  = rsq1 - 1 - dx2;
        if (m1 < 0) continue;                    // bin entirely inside |dx|
        int m0  = rsq - dx2;
        int lo;
        if (m0 <= 0) lo = 0;
        else { int k = isqrt_exact(m0); lo = (k * k == m0) ? k : k + 1; }
        int hi = isqrt_exact(m1);
        if (hi < lo) continue;
        float colsum = 0.f; int npts = 0;
        int hip = (hi < 255) ? hi : 255;         // dy in [lo..hip], ky = 256+dy
        for (int d = lo; d <= hip; d++) colsum += sre[c][FPAD(256 + d)];
        if (hip >= lo) npts += hip - lo + 1;
        int lon = (lo == 0) ? 1 : lo;            // |dy| in [lon..hin], ky = 256-|dy|
        int hin = (hi < 256) ? hi : 256;
        for (int d = lon; d <= hin; d++) colsum += sre[c][FPAD(256 - d)];
        if (hin >= lon) npts += hin - lon + 1;
        float w = (kx == 0 || kx == 256) ? 1.f : 2.f;
        seg  += w * colsum;
        cntv += w * (float)npts;
    }
    g_part[blockIdx.x * 256 + tid] = seg;        // coalesced 1KB per block
    if (b == 0) g_cnt[g * 256 + tid] = cntv;
}

// ------- K3: 2-level coalesced reduce + last-block loss -------
__global__ __launch_bounds__(256) void k_reduce_final(float* __restrict__ out){
    __shared__ float red[256];
    __shared__ int   s_last;
    __shared__ float s_gs, s_rs;
    const int bid = blockIdx.x, tid = threadIdx.x;

    // level 1: sum 16 contiguous partial rows (fully coalesced, MLP=16)
    float s = 0.f;
#pragma unroll
    for (int r = 0; r < 16; r++)
        s += g_part[(bid * 16 + r) * 256 + tid];
    g_part2[bid * 256 + tid] = s;
    __threadfence();
    if (tid == 0){
        unsigned old = atomicAdd(&g_arrive, 1u);
        s_last = (old == 64u) ? 1 : 0;
    }
    __syncthreads();
    if (!s_last) return;
    if (tid == 0) g_arrive = 0;          // reset for next graph replay
    __threadfence();                     // acquire (fence-fence sync)

    float seg = 0.f, cnt = 0.f;
#pragma unroll
    for (int i = 0; i < 65; i++){
        seg += g_part2[i * 256 + tid];
        cnt += g_cnt [i * 256 + tid];
    }

    float gen = 0.f, refv = 0.f;
    if (tid >= 1){
        float denom = fmaxf(cnt, 1.0f) * (float)NB;
        gen  = (cnt > 0.f) ? seg / denom : 0.0f;
        refv = powf((float)tid, -5.0f / 3.0f);
    }

    red[tid] = gen; __syncthreads();
    for (int o = 128; o > 0; o >>= 1){ if (tid < o) red[tid] += red[tid + o]; __syncthreads(); }
    if (tid == 0) s_gs = red[0] + 1e-8f;
    __syncthreads();
    red[tid] = refv; __syncthreads();
    for (int o = 128; o > 0; o >>= 1){ if (tid < o) red[tid] += red[tid + o]; __syncthreads(); }
    if (tid == 0) s_rs = red[0] + 1e-8f;
    __syncthreads();

    float d = (tid >= 1) ? (gen / s_gs - refv / s_rs) : 0.f;
    red[tid] = d * d; __syncthreads();
    for (int o = 128; o > 0; o >>= 1){ if (tid < o) red[tid] += red[tid + o]; __syncthreads(); }
    if (tid == 0) out[0] = red[0] / 255.0f;
}

extern "C" void kernel_launch(void* const* d_in, const int* in_sizes, int n_in,
                              void* d_out, int out_size) {
    (void)in_sizes; (void)n_in; (void)out_size;
    const float* in  = (const float*)d_in[0];
    float*       out = (float*)d_out;

    k_twiddle_init<<<1, 512>>>();
    k_mean_rowfft<<<NB * 64, 256>>>(in);
    k_colfft_bin<<<K2_BLOCKS, 256>>>();
    k_reduce_final<<<65, 256>>>(out);
}

// round 15
// speedup vs baseline: 1.0930x; 1.0930x over previous
#include <cuda_runtime.h>
#include <cuda_bf16.h>
#include <math.h>

// ----------------------------------------------------------------------------
// SpectralLoss on GB300 — register radix-8 FFT + direct global-RED binning.
// K0: zero bins + fill twiddle tables (every launch; graph-replay safe).
// K1: T-mean + packed row-pair FFT + Hermitian split -> g_fft[k=0..256].
// K2: column FFT (4 cols/block); owner-computes bin gather; ONE global
//     atomicAdd per thread into g_seg[256] (g_cnt for b==0). No partials.
// K3: single block computes the loss scalar from the 256 bins.
// ----------------------------------------------------------------------------

#define N512 512
#define NB   16
#define NT   8
#define RS   264                  // g_fft row stride (float2)
#define K2_BLOCKS (NB * 65)       // 1040
#define FPAD(i) ((i) + (((i) >> 6) << 3))   // +8 pad per 64 slots

__device__ float2 g_fft[(size_t)NB * N512 * RS];     // ~17.3 MB
__device__ float  g_seg[256];                        // power bins (RED target)
__device__ float  g_cnt[256];                        // count bins (RED target)
__device__ float2 g_tw1[7 * 64];                     // W512^{t*q}, q=1..7
__device__ float2 g_tw2[8 * 7];                      // W64^{u*r},  r=1..7

__device__ __forceinline__ float2 cadd(float2 a, float2 b){ return make_float2(a.x+b.x, a.y+b.y); }
__device__ __forceinline__ float2 csub(float2 a, float2 b){ return make_float2(a.x-b.x, a.y-b.y); }
__device__ __forceinline__ float2 cmul(float2 a, float2 b){
    return make_float2(a.x*b.x - a.y*b.y, a.x*b.y + a.y*b.x);
}
__device__ __forceinline__ float2 mul_mi(float2 a){ return make_float2(a.y, -a.x); }
__device__ __forceinline__ float2 mul_w81(float2 a){
    const float C = 0.70710678118654752f;
    return make_float2(C*(a.x+a.y), C*(a.y-a.x));
}
__device__ __forceinline__ float2 mul_w83(float2 a){
    const float C = 0.70710678118654752f;
    return make_float2(C*(a.y-a.x), -C*(a.x+a.y));
}

__device__ __forceinline__ void dft8(const float2* a, float2* X){
    float2 t0 = cadd(a[0], a[4]), t1 = cadd(a[1], a[5]);
    float2 t2 = cadd(a[2], a[6]), t3 = cadd(a[3], a[7]);
    float2 u0 = csub(a[0], a[4]);
    float2 u1 = mul_w81(csub(a[1], a[5]));
    float2 u2 = mul_mi (csub(a[2], a[6]));
    float2 u3 = mul_w83(csub(a[3], a[7]));
    float2 s0 = cadd(t0, t2), s1 = cadd(t1, t3);
    float2 d0 = csub(t0, t2), d1 = mul_mi(csub(t1, t3));
    float2 e0 = cadd(u0, u2), e1 = cadd(u1, u3);
    float2 f0 = csub(u0, u2), f1 = mul_mi(csub(u1, u3));
    X[0] = cadd(s0, s1); X[4] = csub(s0, s1);
    X[2] = cadd(d0, d1); X[6] = csub(d0, d1);
    X[1] = cadd(e0, e1); X[5] = csub(e0, e1);
    X[3] = cadd(f0, f1); X[7] = csub(f0, f1);
}

// exact integer isqrt via correctly-rounded float sqrt + fixup (n < 2^20)
__device__ __forceinline__ int isqrt_exact(int n){
    int k = (int)__fsqrt_rn((float)n);
    if (k * k > n) k--;
    else if ((k + 1) * (k + 1) <= n) k++;
    return k;
}

// ---------------- K0: zero bins + twiddle tables ----------------
__global__ void k_init(){
    const int i = threadIdx.x;
    if (i < 256){ g_seg[i] = 0.f; g_cnt[i] = 0.f; }
    if (i < 448){
        int q = (i >> 6) + 1, t = i & 63;
        float ang = -6.2831853071795864f * (float)(t * q) / 512.0f;
        float s, c; sincosf(ang, &s, &c);
        g_tw1[i] = make_float2(c, s);
    }
    if (i < 56){
        int u = i / 7, r = (i % 7) + 1;
        float ang = -6.2831853071795864f * (float)(u * r) / 64.0f;
        float s, c; sincosf(ang, &s, &c);
        g_tw2[i] = make_float2(c, s);
    }
}

// stage 1: a[p] = x[t + 64p] -> y_q[t] stored at 72q+t  (twiddles from g_tw1)
__device__ __forceinline__ void fft_stage1(const float2* a, int t, float* sre, float* sim){
    float2 W[8];
#pragma unroll
    for (int q = 1; q < 8; q++) W[q] = g_tw1[((q - 1) << 6) + t];
    float2 b[8];
    dft8(a, b);
    sre[t] = b[0].x; sim[t] = b[0].y;
#pragma unroll
    for (int q = 1; q < 8; q++){
        float2 c = cmul(b[q], W[q]);
        sre[72*q + t] = c.x; sim[72*q + t] = c.y;
    }
}

// stages 2+3: consumes y in shared, returns X[w] at ky = ky0 + 64w
__device__ __forceinline__ void fft_stage23(float* sre, float* sim, int t,
                                            float2* X, int* ky0_out){
    const int q = t >> 3, u = t & 7;
    float2 W[8];
#pragma unroll
    for (int r = 1; r < 8; r++) W[r] = g_tw2[u * 7 + (r - 1)];
    float2 a[8], b[8];
#pragma unroll
    for (int v = 0; v < 8; v++){
        int idx = 72*q + u + 8*v;
        a[v] = make_float2(sre[idx], sim[idx]);
    }
    dft8(a, b);
    __syncwarp();
    {   // r = 0
        int idx = 72*q + (u ^ ((2*q) & 7));
        sre[idx] = b[0].x; sim[idx] = b[0].y;
    }
#pragma unroll
    for (int r = 1; r < 8; r++){
        float2 c = cmul(b[r], W[r]);
        int swz = (2*q + (r >> 2)) & 7;
        int idx = 72*q + 8*r + (u ^ swz);
        sre[idx] = c.x; sim[idx] = c.y;
    }
    __syncwarp();
    const int r3 = u;
    const int swz = (2*q + (r3 >> 2)) & 7;
#pragma unroll
    for (int uu = 0; uu < 8; uu++){
        int idx = 72*q + 8*r3 + (uu ^ swz);
        a[uu] = make_float2(sre[idx], sim[idx]);
    }
    dft8(a, X);
    *ky0_out = q + 8*r3;
}

// ---------------- K1: T-mean + packed row-pair FFT + Hermitian split ---------
__global__ __launch_bounds__(256) void k_mean_rowfft(const float* __restrict__ in){
    __shared__ float sre[4][584], sim[4][584];
    const int tid  = threadIdx.x;
    const int team = tid >> 6;
    const int t    = tid & 63;
    const int b    = blockIdx.x >> 6;
    const int hp   = ((blockIdx.x & 63) << 2) + team;    // row pair 0..255

    const float* base = in + ((size_t)b * NT * N512 + 2 * hp) * N512;
    float2 a[8];
#pragma unroll
    for (int p = 0; p < 8; p++) a[p] = make_float2(0.f, 0.f);
#pragma unroll
    for (int tt = 0; tt < NT; tt++){
        const float* pe = base + (size_t)tt * (N512 * N512);
#pragma unroll
        for (int p = 0; p < 8; p++){
            a[p].x += pe[t + 64*p];            // even row -> re
            a[p].y += pe[N512 + t + 64*p];     // odd row  -> im
        }
    }
#pragma unroll
    for (int p = 0; p < 8; p++){ a[p].x *= 0.125f; a[p].y *= 0.125f; }

    fft_stage1(a, t, sre[team], sim[team]);
    __syncthreads();
    float2 X[8]; int ky0;
    fft_stage23(sre[team], sim[team], t, X, &ky0);
    __syncthreads();
#pragma unroll
    for (int w = 0; w < 8; w++){
        sre[team][ky0 + 72*w] = X[w].x;        // = FPAD(ky0 + 64w)
        sim[team][ky0 + 72*w] = X[w].y;
    }
    __syncthreads();

    // Hermitian split: Z = Fe + i*Fo
    float2* oute = g_fft + ((size_t)b * N512 + 2 * hp) * RS;
    float2* outo = oute + RS;
    for (int k = t; k <= 256; k += 64){
        int m = (N512 - k) & (N512 - 1);
        float2 zk = make_float2(sre[team][FPAD(k)], sim[team][FPAD(k)]);
        float2 zm = make_float2(sre[team][FPAD(m)], sim[team][FPAD(m)]);
        oute[k] = make_float2(0.5f*(zk.x + zm.x), 0.5f*(zk.y - zm.y));
        outo[k] = make_float2(0.5f*(zk.y + zm.y), 0.5f*(zm.x - zk.x));
    }
}

// ---------------- K2: column FFT + owner-computes gather + global RED --------
__global__ __launch_bounds__(256) void k_colfft_bin(){
    __shared__ float sre[4][584], sim[4][584];
    const int tid = threadIdx.x;
    const int b   = blockIdx.x / 65;
    const int g   = blockIdx.x % 65;
    const int kx0 = g << 2;

    const float2* src = g_fft + (size_t)b * (N512 * RS);
#pragma unroll
    for (int k = 0; k < 8; k++){
        int idx = tid + (k << 8);
        int row = idx >> 2, c = idx & 3;
        int kx  = kx0 + c;
        float2 v = (kx <= 256) ? src[(size_t)row * RS + kx] : make_float2(0.f, 0.f);
        sre[c][FPAD(row)] = v.x; sim[c][FPAD(row)] = v.y;
    }
    __syncthreads();

    const int team = tid >> 6, t = tid & 63;
    float2 a[8];
#pragma unroll
    for (int p = 0; p < 8; p++)
        a[p] = make_float2(sre[team][t + 72*p], sim[team][t + 72*p]);  // FPAD(t+64p)
    fft_stage1(a, t, sre[team], sim[team]);
    __syncthreads();
    float2 X[8]; int ky0;
    fft_stage23(sre[team], sim[team], t, X, &ky0);
    __syncthreads();
    // write RAW power back into sre[team], indexed by ky
#pragma unroll
    for (int w = 0; w < 8; w++)
        sre[team][ky0 + 72*w] = X[w].x * X[w].x + X[w].y * X[w].y;  // = FPAD(ky0+64w)
    __syncthreads();

    // owner-computes: thread r gathers its bin's exact ky-ranges per column,
    // then ONE global atomicAdd into g_seg[r] (and g_cnt[r] for b==0).
    const int r = tid;
    const int rsq  = r * r;
    const int rsq1 = (r + 1) * (r + 1);
    float seg = 0.f, cntv = 0.f;
#pragma unroll
    for (int c = 0; c < 4; c++){
        int kx = kx0 + c;
        if (kx > 256) break;
        int dx  = kx - 256;
        int dx2 = dx * dx;
        int m1  = rsq1 - 1 - dx2;
        if (m1 < 0) continue;
        int m0  = rsq - dx2;
        int lo;
        if (m0 <= 0) lo = 0;
        else { int k = isqrt_exact(m0); lo = (k * k == m0) ? k : k + 1; }
        int hi = isqrt_exact(m1);
        if (hi < lo) continue;
        float colsum = 0.f; int npts = 0;
        int hip = (hi < 255) ? hi : 255;         // dy in [lo..hip], ky = 256+dy
        for (int d = lo; d <= hip; d++) colsum += sre[c][FPAD(256 + d)];
        if (hip >= lo) npts += hip - lo + 1;
        int lon = (lo == 0) ? 1 : lo;            // |dy| in [lon..hin], ky = 256-|dy|
        int hin = (hi < 256) ? hi : 256;
        for (int d = lon; d <= hin; d++) colsum += sre[c][FPAD(256 - d)];
        if (hin >= lon) npts += hin - lon + 1;
        float w = (kx == 0 || kx == 256) ? 1.f : 2.f;
        seg  += w * colsum;
        cntv += w * (float)npts;
    }
    if (seg != 0.f) atomicAdd(&g_seg[r], seg);
    if (b == 0 && cntv != 0.f) atomicAdd(&g_cnt[r], cntv);
}

// ------- K3: single-block loss scalar (kernel boundary = full fence) -------
__global__ __launch_bounds__(256) void k_final(float* __restrict__ out){
    __shared__ float red[256];
    __shared__ float s_gs, s_rs;
    const int tid = threadIdx.x;

    float seg = g_seg[tid];
    float cnt = g_cnt[tid];

    float gen = 0.f, refv = 0.f;
    if (tid >= 1){
        float denom = fmaxf(cnt, 1.0f) * (float)NB;
        gen  = (cnt > 0.f) ? seg / denom : 0.0f;
        refv = powf((float)tid, -5.0f / 3.0f);
    }

    red[tid] = gen; __syncthreads();
    for (int o = 128; o > 0; o >>= 1){ if (tid < o) red[tid] += red[tid + o]; __syncthreads(); }
    if (tid == 0) s_gs = red[0] + 1e-8f;
    __syncthreads();
    red[tid] = refv; __syncthreads();
    for (int o = 128; o > 0; o >>= 1){ if (tid < o) red[tid] += red[tid + o]; __syncthreads(); }
    if (tid == 0) s_rs = red[0] + 1e-8f;
    __syncthreads();

    float d = (tid >= 1) ? (gen / s_gs - refv / s_rs) : 0.f;
    red[tid] = d * d; __syncthreads();
    for (int o = 128; o > 0; o >>= 1){ if (tid < o) red[tid] += red[tid + o]; __syncthreads(); }
    if (tid == 0) out[0] = red[0] / 255.0f;
}

extern "C" void kernel_launch(void* const* d_in, const int* in_sizes, int n_in,
                              void* d_out, int out_size) {
    (void)in_sizes; (void)n_in; (void)out_size;
    const float* in  = (const float*)d_in[0];
    float*       out = (float*)d_out;

    k_init<<<1, 512>>>();
    k_mean_rowfft<<<NB * 64, 256>>>(in);
    k_colfft_bin<<<K2_BLOCKS, 256>>>();
    k_final<<<1, 256>>>(out);
}

// round 16
// speedup vs baseline: 1.1774x; 1.0773x over previous
#include <cuda_runtime.h>
#include <cuda_bf16.h>
#include <math.h>

// ----------------------------------------------------------------------------
// SpectralLoss on GB300 — fused row+column FFT with per-image pipelining.
// K0: zero bins/counters + twiddle tables (every launch; graph-replay safe).
// KF (fused): blocks 0..1023 = row-FFT role (T-mean + row-pair FFT + Hermitian
//     split -> g_fft, then release g_rowdone[b]); blocks 1024..2063 = column
//     role (spin on g_rowdone[b]==64, __ldcg loads, column FFT, owner-computes
//     radial gather, global RED into g_seg/g_cnt). Column work overlaps the
//     DRAM-bound row streaming of later images.
// K3: single block computes the loss scalar.
// ----------------------------------------------------------------------------

#define N512 512
#define NB   16
#define NT   8
#define RS   264                  // g_fft row stride (float2)
#define K1_BLOCKS (NB * 64)       // 1024
#define K2_BLOCKS (NB * 65)       // 1040
#define FPAD(i) ((i) + (((i) >> 6) << 3))   // +8 pad per 64 slots

__device__ float2 g_fft[(size_t)NB * N512 * RS];     // ~17.3 MB
__device__ float  g_seg[256];                        // power bins (RED target)
__device__ float  g_cnt[256];                        // count bins (RED target)
__device__ unsigned g_rowdone[NB];                   // per-image K1 completion
__device__ float2 g_tw1[7 * 64];                     // W512^{t*q}, q=1..7
__device__ float2 g_tw2[8 * 7];                      // W64^{u*r},  r=1..7

__device__ __forceinline__ float2 cadd(float2 a, float2 b){ return make_float2(a.x+b.x, a.y+b.y); }
__device__ __forceinline__ float2 csub(float2 a, float2 b){ return make_float2(a.x-b.x, a.y-b.y); }
__device__ __forceinline__ float2 cmul(float2 a, float2 b){
    return make_float2(a.x*b.x - a.y*b.y, a.x*b.y + a.y*b.x);
}
__device__ __forceinline__ float2 mul_mi(float2 a){ return make_float2(a.y, -a.x); }
__device__ __forceinline__ float2 mul_w81(float2 a){
    const float C = 0.70710678118654752f;
    return make_float2(C*(a.x+a.y), C*(a.y-a.x));
}
__device__ __forceinline__ float2 mul_w83(float2 a){
    const float C = 0.70710678118654752f;
    return make_float2(C*(a.y-a.x), -C*(a.x+a.y));
}

__device__ __forceinline__ void dft8(const float2* a, float2* X){
    float2 t0 = cadd(a[0], a[4]), t1 = cadd(a[1], a[5]);
    float2 t2 = cadd(a[2], a[6]), t3 = cadd(a[3], a[7]);
    float2 u0 = csub(a[0], a[4]);
    float2 u1 = mul_w81(csub(a[1], a[5]));
    float2 u2 = mul_mi (csub(a[2], a[6]));
    float2 u3 = mul_w83(csub(a[3], a[7]));
    float2 s0 = cadd(t0, t2), s1 = cadd(t1, t3);
    float2 d0 = csub(t0, t2), d1 = mul_mi(csub(t1, t3));
    float2 e0 = cadd(u0, u2), e1 = cadd(u1, u3);
    float2 f0 = csub(u0, u2), f1 = mul_mi(csub(u1, u3));
    X[0] = cadd(s0, s1); X[4] = csub(s0, s1);
    X[2] = cadd(d0, d1); X[6] = csub(d0, d1);
    X[1] = cadd(e0, e1); X[5] = csub(e0, e1);
    X[3] = cadd(f0, f1); X[7] = csub(f0, f1);
}

// exact integer isqrt via correctly-rounded float sqrt + fixup (n < 2^20)
__device__ __forceinline__ int isqrt_exact(int n){
    int k = (int)__fsqrt_rn((float)n);
    if (k * k > n) k--;
    else if ((k + 1) * (k + 1) <= n) k++;
    return k;
}

// ---------------- K0: zero bins/counters + twiddle tables ----------------
__global__ void k_init(){
    const int i = threadIdx.x;
    if (i < 256){ g_seg[i] = 0.f; g_cnt[i] = 0.f; }
    if (i < NB) g_rowdone[i] = 0u;
    if (i < 448){
        int q = (i >> 6) + 1, t = i & 63;
        float ang = -6.2831853071795864f * (float)(t * q) / 512.0f;
        float s, c; sincosf(ang, &s, &c);
        g_tw1[i] = make_float2(c, s);
    }
    if (i < 56){
        int u = i / 7, r = (i % 7) + 1;
        float ang = -6.2831853071795864f * (float)(u * r) / 64.0f;
        float s, c; sincosf(ang, &s, &c);
        g_tw2[i] = make_float2(c, s);
    }
}

// stage 1: a[p] = x[t + 64p] -> y_q[t] stored at 72q+t  (twiddles from g_tw1)
__device__ __forceinline__ void fft_stage1(const float2* a, int t, float* sre, float* sim){
    float2 W[8];
#pragma unroll
    for (int q = 1; q < 8; q++) W[q] = g_tw1[((q - 1) << 6) + t];
    float2 b[8];
    dft8(a, b);
    sre[t] = b[0].x; sim[t] = b[0].y;
#pragma unroll
    for (int q = 1; q < 8; q++){
        float2 c = cmul(b[q], W[q]);
        sre[72*q + t] = c.x; sim[72*q + t] = c.y;
    }
}

// stages 2+3: consumes y in shared, returns X[w] at ky = ky0 + 64w
__device__ __forceinline__ void fft_stage23(float* sre, float* sim, int t,
                                            float2* X, int* ky0_out){
    const int q = t >> 3, u = t & 7;
    float2 W[8];
#pragma unroll
    for (int r = 1; r < 8; r++) W[r] = g_tw2[u * 7 + (r - 1)];
    float2 a[8], b[8];
#pragma unroll
    for (int v = 0; v < 8; v++){
        int idx = 72*q + u + 8*v;
        a[v] = make_float2(sre[idx], sim[idx]);
    }
    dft8(a, b);
    __syncwarp();
    {   // r = 0
        int idx = 72*q + (u ^ ((2*q) & 7));
        sre[idx] = b[0].x; sim[idx] = b[0].y;
    }
#pragma unroll
    for (int r = 1; r < 8; r++){
        float2 c = cmul(b[r], W[r]);
        int swz = (2*q + (r >> 2)) & 7;
        int idx = 72*q + 8*r + (u ^ swz);
        sre[idx] = c.x; sim[idx] = c.y;
    }
    __syncwarp();
    const int r3 = u;
    const int swz = (2*q + (r3 >> 2)) & 7;
#pragma unroll
    for (int uu = 0; uu < 8; uu++){
        int idx = 72*q + 8*r3 + (uu ^ swz);
        a[uu] = make_float2(sre[idx], sim[idx]);
    }
    dft8(a, X);
    *ky0_out = q + 8*r3;
}

// ---------------- fused kernel: row role (bid<1024) | column role ------------
__global__ __launch_bounds__(256) void k_fft_fused(const float* __restrict__ in){
    __shared__ float sre[4][584], sim[4][584];
    const int tid = threadIdx.x;

    if (blockIdx.x < K1_BLOCKS){
        // ================= row-FFT role =================
        const int team = tid >> 6;
        const int t    = tid & 63;
        const int b    = blockIdx.x >> 6;
        const int hp   = ((blockIdx.x & 63) << 2) + team;    // row pair 0..255

        const float* base = in + ((size_t)b * NT * N512 + 2 * hp) * N512;
        float2 a[8];
#pragma unroll
        for (int p = 0; p < 8; p++) a[p] = make_float2(0.f, 0.f);
#pragma unroll
        for (int tt = 0; tt < NT; tt++){
            const float* pe = base + (size_t)tt * (N512 * N512);
#pragma unroll
            for (int p = 0; p < 8; p++){
                a[p].x += pe[t + 64*p];            // even row -> re
                a[p].y += pe[N512 + t + 64*p];     // odd row  -> im
            }
        }
#pragma unroll
        for (int p = 0; p < 8; p++){ a[p].x *= 0.125f; a[p].y *= 0.125f; }

        fft_stage1(a, t, sre[team], sim[team]);
        __syncthreads();
        float2 X[8]; int ky0;
        fft_stage23(sre[team], sim[team], t, X, &ky0);
        __syncthreads();
#pragma unroll
        for (int w = 0; w < 8; w++){
            sre[team][ky0 + 72*w] = X[w].x;        // = FPAD(ky0 + 64w)
            sim[team][ky0 + 72*w] = X[w].y;
        }
        __syncthreads();

        // Hermitian split: Z = Fe + i*Fo
        float2* oute = g_fft + ((size_t)b * N512 + 2 * hp) * RS;
        float2* outo = oute + RS;
        for (int k = t; k <= 256; k += 64){
            int m = (N512 - k) & (N512 - 1);
            float2 zk = make_float2(sre[team][FPAD(k)], sim[team][FPAD(k)]);
            float2 zm = make_float2(sre[team][FPAD(m)], sim[team][FPAD(m)]);
            oute[k] = make_float2(0.5f*(zk.x + zm.x), 0.5f*(zk.y - zm.y));
            outo[k] = make_float2(0.5f*(zk.y + zm.y), 0.5f*(zm.x - zk.x));
        }
        // release: rows of image b visible before counter bump
        __threadfence();
        __syncthreads();
        if (tid == 0) atomicAdd(&g_rowdone[b], 1u);
    } else {
        // ================= column-FFT role =================
        const int kb  = blockIdx.x - K1_BLOCKS;
        const int b   = kb / 65;
        const int g   = kb % 65;
        const int kx0 = g << 2;

        if (tid == 0){
            while (atomicAdd(&g_rowdone[b], 0u) < 64u) __nanosleep(128);
        }
        __syncthreads();                       // broadcast readiness
        __threadfence();                       // acquire side of fence-fence

        const float2* src = g_fft + (size_t)b * (N512 * RS);
#pragma unroll
        for (int k = 0; k < 8; k++){
            int idx = tid + (k << 8);
            int row = idx >> 2, c = idx & 3;
            int kx  = kx0 + c;
            float2 v = (kx <= 256) ? __ldcg(&src[(size_t)row * RS + kx])
                                   : make_float2(0.f, 0.f);
            sre[c][FPAD(row)] = v.x; sim[c][FPAD(row)] = v.y;
        }
        __syncthreads();

        const int team = tid >> 6, t = tid & 63;
        float2 a[8];
#pragma unroll
        for (int p = 0; p < 8; p++)
            a[p] = make_float2(sre[team][t + 72*p], sim[team][t + 72*p]);
        fft_stage1(a, t, sre[team], sim[team]);
        __syncthreads();
        float2 X[8]; int ky0;
        fft_stage23(sre[team], sim[team], t, X, &ky0);
        __syncthreads();
#pragma unroll
        for (int w = 0; w < 8; w++)
            sre[team][ky0 + 72*w] = X[w].x * X[w].x + X[w].y * X[w].y;
        __syncthreads();

        // owner-computes gather + global RED
        const int r = tid;
        const int rsq  = r * r;
        const int rsq1 = (r + 1) * (r + 1);
        float seg = 0.f, cntv = 0.f;
#pragma unroll
        for (int c = 0; c < 4; c++){
            int kx = kx0 + c;
            if (kx > 256) break;
            int dx  = kx - 256;
            int dx2 = dx * dx;
            int m1  = rsq1 - 1 - dx2;
            if (m1 < 0) continue;
            int m0  = rsq - dx2;
            int lo;
            if (m0 <= 0) lo = 0;
            else { int k = isqrt_exact(m0); lo = (k * k == m0) ? k : k + 1; }
            int hi = isqrt_exact(m1);
            if (hi < lo) continue;
            float colsum = 0.f; int npts = 0;
            int hip = (hi < 255) ? hi : 255;
            for (int d = lo; d <= hip; d++) colsum += sre[c][FPAD(256 + d)];
            if (hip >= lo) npts += hip - lo + 1;
            int lon = (lo == 0) ? 1 : lo;
            int hin = (hi < 256) ? hi : 256;
            for (int d = lon; d <= hin; d++) colsum += sre[c][FPAD(256 - d)];
            if (hin >= lon) npts += hin - lon + 1;
            float w = (kx == 0 || kx == 256) ? 1.f : 2.f;
            seg  += w * colsum;
            cntv += w * (float)npts;
        }
        if (seg != 0.f) atomicAdd(&g_seg[r], seg);
        if (b == 0 && cntv != 0.f) atomicAdd(&g_cnt[r], cntv);
    }
}

// ------- K3: single-block loss scalar (kernel boundary = full fence) -------
__global__ __launch_bounds__(256) void k_final(float* __restrict__ out){
    __shared__ float red[256];
    __shared__ float s_gs, s_rs;
    const int tid = threadIdx.x;

    float seg = g_seg[tid];
    float cnt = g_cnt[tid];

    float gen = 0.f, refv = 0.f;
    if (tid >= 1){
        float denom = fmaxf(cnt, 1.0f) * (float)NB;
        gen  = (cnt > 0.f) ? seg / denom : 0.0f;
        refv = powf((float)tid, -5.0f / 3.0f);
    }

    red[tid] = gen; __syncthreads();
    for (int o = 128; o > 0; o >>= 1){ if (tid < o) red[tid] += red[tid + o]; __syncthreads(); }
    if (tid == 0) s_gs = red[0] + 1e-8f;
    __syncthreads();
    red[tid] = refv; __syncthreads();
    for (int o = 128; o > 0; o >>= 1){ if (tid < o) red[tid] += red[tid + o]; __syncthreads(); }
    if (tid == 0) s_rs = red[0] + 1e-8f;
    __syncthreads();

    float d = (tid >= 1) ? (gen / s_gs - refv / s_rs) : 0.f;
    red[tid] = d * d; __syncthreads();
    for (int o = 128; o > 0; o >>= 1){ if (tid < o) red[tid] += red[tid + o]; __syncthreads(); }
    if (tid == 0) out[0] = red[0] / 255.0f;
}

extern "C" void kernel_launch(void* const* d_in, const int* in_sizes, int n_in,
                              void* d_out, int out_size) {
    (void)in_sizes; (void)n_in; (void)out_size;
    const float* in  = (const float*)d_in[0];
    float*       out = (float*)d_out;

    k_init<<<1, 512>>>();
    k_fft_fused<<<K1_BLOCKS + K2_BLOCKS, 256>>>(in);
    k_final<<<1, 256>>>(out);
}